// round 3
// baseline (speedup 1.0000x reference)
#include <cuda_runtime.h>
#include <cstdint>

// Problem constants
#define B_ROWS    1024
#define IN_FEAT   76800
#define IN_G      19200     // IN_FEAT/4 (float4 / int8x4 groups)
#define OUT_FEAT  10
#define W_ELEMS   (OUT_FEAT * IN_FEAT)   // 768000
#define W_G       (OUT_FEAT * IN_G)      // 192000 packed groups

// quant kernel
#define QT        768                    // threads; 19200/768 = 25 float4/thread
#define QK        25

// gemv kernel: 8 slices x 37 rowblocks = 296 CTAs = 2/SM, one wave
#define NSLICE    8
#define SLICE_G   (IN_G / NSLICE)        // 2400 groups
#define GT        480                    // threads
#define GPT       (SLICE_G / GT)         // 5 k-steps/thread
#define K_REG     2
#define K_SMEM    (GPT - K_REG)          // 3
#define ROWBLKS   37

// wsum reduction
#define WSUM_BLOCKS 125
#define WSUM_THREADS 256

// ---------------- device scratch (static, allocation-free) ----------------
__device__ float    g_wpart[WSUM_BLOCKS];
__device__ float    g_wscale;               // 1/clip(mean|W|,eps)
__device__ float    g_winv;                 // clip(mean|W|,eps)
__device__ float    g_rowscale[B_ROWS];     // 127/clip(rowmax,eps)
__device__ unsigned g_tw[W_G];              // ternary weights, packed int8x4, [o][g]
__device__ unsigned g_q[B_ROWS * IN_G];     // quantized activations, packed int8x4
__device__ int      g_dot[B_ROWS * OUT_FEAT];

// ---------------- kernel 0: zero g_dot (every replay) ----------------
__global__ void k_init(void) {
    g_dot[blockIdx.x * 1024 + threadIdx.x] = 0;   // grid 10 x 1024
}

// ---------------- kernel 1: sum |W| ----------------
__global__ void k_wsum(const float4* __restrict__ w4) {
    float s = 0.f;
    int idx = blockIdx.x * WSUM_THREADS + threadIdx.x;
    #pragma unroll
    for (int k = 0; k < 6; k++) {   // 125*256*6 = 192000 exactly
        float4 v = w4[idx + k * WSUM_BLOCKS * WSUM_THREADS];
        s += fabsf(v.x) + fabsf(v.y) + fabsf(v.z) + fabsf(v.w);
    }
    #pragma unroll
    for (int d = 16; d; d >>= 1) s += __shfl_down_sync(0xffffffffu, s, d);
    __shared__ float red[8];
    int warp = threadIdx.x >> 5, lane = threadIdx.x & 31;
    if (lane == 0) red[warp] = s;
    __syncthreads();
    if (threadIdx.x < 8) {
        float v = red[threadIdx.x];
        #pragma unroll
        for (int d = 4; d; d >>= 1) v += __shfl_down_sync(0xffu, v, d);
        if (threadIdx.x == 0) g_wpart[blockIdx.x] = v;
    }
}

// ---------------- kernel 2: finalize wscale ----------------
__global__ void k_wscale(void) {
    float s = (threadIdx.x < WSUM_BLOCKS) ? g_wpart[threadIdx.x] : 0.f;
    #pragma unroll
    for (int d = 16; d; d >>= 1) s += __shfl_down_sync(0xffffffffu, s, d);
    __shared__ float red[4];
    int warp = threadIdx.x >> 5, lane = threadIdx.x & 31;
    if (lane == 0) red[warp] = s;
    __syncthreads();
    if (threadIdx.x == 0) {
        float total = red[0] + red[1] + red[2] + red[3];
        float mean = fmaxf(total / (float)W_ELEMS, 1e-5f);
        g_winv = mean;
        g_wscale = 1.f / mean;
    }
}

// ---------------- kernel 3: ternarize W into packed int8x4 ----------------
__global__ void k_ternary(const float4* __restrict__ w4) {
    int i = blockIdx.x * 256 + threadIdx.x;   // grid 750*256 = 192000
    float ws = g_wscale;
    float4 v = w4[i];
    int t0 = (int)fminf(1.f, fmaxf(-1.f, rintf(v.x * ws)));
    int t1 = (int)fminf(1.f, fmaxf(-1.f, rintf(v.y * ws)));
    int t2 = (int)fminf(1.f, fmaxf(-1.f, rintf(v.z * ws)));
    int t3 = (int)fminf(1.f, fmaxf(-1.f, rintf(v.w * ws)));
    g_tw[i] = (unsigned)((t0 & 0xFF) | ((t1 & 0xFF) << 8) | ((t2 & 0xFF) << 16) | (t3 << 24));
}

// magic-number quantize of a float4 into packed int8x4.
// FMUL+FADD(1.5*2^23) reproduces round-half-even of fl(x*s) exactly for |x*s|<=127.
__device__ __forceinline__ unsigned quant_pack(float4 v, float as) {
    float f0 = __fadd_rn(__fmul_rn(v.x, as), 12582912.f);
    float f1 = __fadd_rn(__fmul_rn(v.y, as), 12582912.f);
    float f2 = __fadd_rn(__fmul_rn(v.z, as), 12582912.f);
    float f3 = __fadd_rn(__fmul_rn(v.w, as), 12582912.f);
    unsigned p01 = __byte_perm(__float_as_uint(f0), __float_as_uint(f1), 0x0040);
    unsigned p23 = __byte_perm(__float_as_uint(f2), __float_as_uint(f3), 0x0040);
    return __byte_perm(p01, p23, 0x5410);
}

// ---------------- kernel 4: per-row absmax + quantize + write int8 ----------------
// One block per row. Pass 1 streams the row (DRAM); pass 2 re-reads it from L2
// (resident window: 2 blocks/SM x 148 SMs x 307KB = 91MB < L2) and writes int8x4.
__global__ void __launch_bounds__(QT, 2) k_quant(const float4* __restrict__ x4) {
    const int row = blockIdx.x;
    const int tid = threadIdx.x;
    const float4* xr = x4 + (size_t)row * IN_G;

    // pass 1: absmax
    float m = 0.f;
    #pragma unroll 5
    for (int k = 0; k < QK; k++) {
        float4 v = xr[tid + k * QT];
        m = fmaxf(m, fmaxf(fmaxf(fabsf(v.x), fabsf(v.y)),
                           fmaxf(fabsf(v.z), fabsf(v.w))));
    }
    #pragma unroll
    for (int d = 16; d; d >>= 1) m = fmaxf(m, __shfl_down_sync(0xffffffffu, m, d));
    __shared__ float red[QT / 32];
    __shared__ float s_as;
    int warp = tid >> 5, lane = tid & 31;
    if (lane == 0) red[warp] = m;
    __syncthreads();
    if (tid < 32) {
        float v = (tid < QT / 32) ? red[tid] : 0.f;
        #pragma unroll
        for (int d = 16; d; d >>= 1) v = fmaxf(v, __shfl_down_sync(0xffffffffu, v, d));
        if (tid == 0) {
            float asc = 127.f / fmaxf(v, 1e-5f);
            s_as = asc;
            g_rowscale[row] = asc;
        }
    }
    __syncthreads();
    const float as = s_as;

    // pass 2: re-read (L2 hits), quantize, write packed int8
    unsigned* qr = g_q + (size_t)row * IN_G;
    #pragma unroll 5
    for (int k = 0; k < QK; k++)
        qr[tid + k * QT] = quant_pack(xr[tid + k * QT], as);
}

// ---------------- kernel 5: int8 ternary GEMV, no intra-loop syncs ----------------
// grid (NSLICE=8, ROWBLKS=37) = 296 CTAs = 2/SM. Weights slice: 2 k-steps in
// registers, 3 in smem. Warp-local reduce + integer RED into g_dot.
__global__ void __launch_bounds__(GT, 2) k_gemv(void) {
    __shared__ unsigned sw[OUT_FEAT * K_SMEM * GT];   // 57.6 KB

    const int s = blockIdx.x;
    const int rb = blockIdx.y;
    const int tid = threadIdx.x;
    const int lane = tid & 31;
    const int gbase = s * SLICE_G;

    // one-time weight staging
    unsigned wreg[K_REG][OUT_FEAT];
    #pragma unroll
    for (int k = 0; k < K_REG; k++)
        #pragma unroll
        for (int o = 0; o < OUT_FEAT; o++)
            wreg[k][o] = g_tw[o * IN_G + gbase + k * GT + tid];
    #pragma unroll
    for (int o = 0; o < OUT_FEAT; o++)
        #pragma unroll
        for (int kk = 0; kk < K_SMEM; kk++)
            sw[(o * K_SMEM + kk) * GT + tid] =
                g_tw[o * IN_G + gbase + (K_REG + kk) * GT + tid];
    __syncthreads();

    for (int row = rb; row < B_ROWS; row += ROWBLKS) {
        const unsigned* qr = g_q + (size_t)row * IN_G + gbase;

        unsigned a[GPT];
        #pragma unroll
        for (int k = 0; k < GPT; k++) a[k] = qr[k * GT + tid];

        int acc[OUT_FEAT];
        #pragma unroll
        for (int o = 0; o < OUT_FEAT; o++) acc[o] = 0;
        #pragma unroll
        for (int k = 0; k < K_REG; k++)
            #pragma unroll
            for (int o = 0; o < OUT_FEAT; o++)
                acc[o] = __dp4a((int)a[k], (int)wreg[k][o], acc[o]);
        #pragma unroll
        for (int kk = 0; kk < K_SMEM; kk++)
            #pragma unroll
            for (int o = 0; o < OUT_FEAT; o++)
                acc[o] = __dp4a((int)a[K_REG + kk],
                                (int)sw[(o * K_SMEM + kk) * GT + tid], acc[o]);

        // warp-local butterfly reduce (all 10 simultaneously), then RED
        #pragma unroll
        for (int o = 0; o < OUT_FEAT; o++) {
            #pragma unroll
            for (int d = 16; d; d >>= 1)
                acc[o] += __shfl_down_sync(0xffffffffu, acc[o], d);
        }
        if (lane == 0) {
            int* dst = g_dot + row * OUT_FEAT;
            #pragma unroll
            for (int o = 0; o < OUT_FEAT; o++) atomicAdd(dst + o, acc[o]);
        }
    }
}

// ---------------- kernel 6: scale, bias, softmax ----------------
__global__ void k_finish(const float* __restrict__ bias, float* __restrict__ out) {
    int row = blockIdx.x * 128 + threadIdx.x;   // grid 8 x 128
    float inv_as = 1.f / g_rowscale[row];
    float coef = inv_as * g_winv;
    const int* dp = g_dot + row * OUT_FEAT;
    float logit[OUT_FEAT];
    float m = -3.4e38f;
    #pragma unroll
    for (int o = 0; o < OUT_FEAT; o++) {
        logit[o] = coef * (float)dp[o] + bias[o];
        m = fmaxf(m, logit[o]);
    }
    float ssum = 0.f;
    #pragma unroll
    for (int o = 0; o < OUT_FEAT; o++) { logit[o] = expf(logit[o] - m); ssum += logit[o]; }
    float inv_s = 1.f / ssum;
    #pragma unroll
    for (int o = 0; o < OUT_FEAT; o++) out[row * OUT_FEAT + o] = logit[o] * inv_s;
}

// ---------------- launch ----------------
extern "C" void kernel_launch(void* const* d_in, const int* in_sizes, int n_in,
                              void* d_out, int out_size) {
    const float4* x4 = (const float4*)d_in[0];   // [1024,3,160,160] fp32
    const float4* w4 = (const float4*)d_in[1];   // [10,76800] fp32
    const float*  b  = (const float*)d_in[2];    // [10]
    float* out = (float*)d_out;

    k_init<<<10, 1024>>>();
    k_wsum<<<WSUM_BLOCKS, WSUM_THREADS>>>(w4);
    k_wscale<<<1, 128>>>();
    k_ternary<<<W_G / 256, 256>>>(w4);
    k_quant<<<B_ROWS, QT>>>(x4);
    dim3 ggrid(NSLICE, ROWBLKS);
    k_gemv<<<ggrid, GT>>>();
    k_finish<<<B_ROWS / 128, 128>>>(b, out);
}

// round 4
// speedup vs baseline: 1.4643x; 1.4643x over previous
#include <cuda_runtime.h>
#include <cstdint>

// Problem constants
#define B_ROWS    1024
#define IN_FEAT   76800
#define IN_G      19200     // IN_FEAT/4 (float4 / int8x4 groups)
#define OUT_FEAT  10
#define W_ELEMS   (OUT_FEAT * IN_FEAT)   // 768000
#define W_G       (OUT_FEAT * IN_G)      // 192000 packed groups

// rowmax kernel
#define QT        768
#define QK        25                     // 25*768 = 19200

// gemv kernel: 8 slices x 37 rowblocks = 296 CTAs = 2/SM
#define NSLICE    8
#define SLICE_G   (IN_G / NSLICE)        // 2400 groups
#define GT        480
#define GPT       (SLICE_G / GT)         // 5 k-steps/thread
#define ROWBLKS   37
#define GEMV_SMEM (OUT_FEAT * GPT * GT * 4)   // 96000 bytes

// wsum reduction
#define WSUM_BLOCKS 125
#define WSUM_THREADS 256

// ---------------- device scratch (static, allocation-free) ----------------
__device__ float    g_wpart[WSUM_BLOCKS];
__device__ float    g_wscale;               // 1/clip(mean|W|,eps)
__device__ float    g_winv;                 // clip(mean|W|,eps)
__device__ float    g_rowscale[B_ROWS];     // 127/clip(rowmax,eps)
__device__ unsigned g_tw[W_G];              // ternary weights, packed int8x4, [o][g]
__device__ int      g_dot[B_ROWS * OUT_FEAT];

// ---------------- kernel 1: sum |W| ----------------
__global__ void k_wsum(const float4* __restrict__ w4) {
    float s = 0.f;
    int idx = blockIdx.x * WSUM_THREADS + threadIdx.x;
    #pragma unroll
    for (int k = 0; k < 6; k++) {   // 125*256*6 = 192000 exactly
        float4 v = w4[idx + k * WSUM_BLOCKS * WSUM_THREADS];
        s += fabsf(v.x) + fabsf(v.y) + fabsf(v.z) + fabsf(v.w);
    }
    #pragma unroll
    for (int d = 16; d; d >>= 1) s += __shfl_down_sync(0xffffffffu, s, d);
    __shared__ float red[8];
    int warp = threadIdx.x >> 5, lane = threadIdx.x & 31;
    if (lane == 0) red[warp] = s;
    __syncthreads();
    if (threadIdx.x < 8) {
        float v = red[threadIdx.x];
        #pragma unroll
        for (int d = 4; d; d >>= 1) v += __shfl_down_sync(0xffu, v, d);
        if (threadIdx.x == 0) g_wpart[blockIdx.x] = v;
    }
}

// ---------------- kernel 2: finalize wscale ----------------
__global__ void k_wscale(void) {
    float s = (threadIdx.x < WSUM_BLOCKS) ? g_wpart[threadIdx.x] : 0.f;
    #pragma unroll
    for (int d = 16; d; d >>= 1) s += __shfl_down_sync(0xffffffffu, s, d);
    __shared__ float red[4];
    int warp = threadIdx.x >> 5, lane = threadIdx.x & 31;
    if (lane == 0) red[warp] = s;
    __syncthreads();
    if (threadIdx.x == 0) {
        float total = red[0] + red[1] + red[2] + red[3];
        float mean = fmaxf(total / (float)W_ELEMS, 1e-5f);
        g_winv = mean;
        g_wscale = 1.f / mean;
    }
}

// ---------------- kernel 3: ternarize W into packed int8x4 ----------------
__global__ void k_ternary(const float4* __restrict__ w4) {
    int i = blockIdx.x * 256 + threadIdx.x;   // grid 750*256 = 192000
    float ws = g_wscale;
    float4 v = w4[i];
    int t0 = (int)fminf(1.f, fmaxf(-1.f, rintf(v.x * ws)));
    int t1 = (int)fminf(1.f, fmaxf(-1.f, rintf(v.y * ws)));
    int t2 = (int)fminf(1.f, fmaxf(-1.f, rintf(v.z * ws)));
    int t3 = (int)fminf(1.f, fmaxf(-1.f, rintf(v.w * ws)));
    g_tw[i] = (unsigned)((t0 & 0xFF) | ((t1 & 0xFF) << 8) | ((t2 & 0xFF) << 16) | (t3 << 24));
}

// ---------------- kernel 4: per-row absmax (at DRAM roofline) ----------------
// Also zeroes g_dot for this row (replaces a separate init kernel).
__global__ void __launch_bounds__(QT) k_rowmax(const float4* __restrict__ x4) {
    const int row = blockIdx.x;
    const int tid = threadIdx.x;
    if (tid < OUT_FEAT) g_dot[row * OUT_FEAT + tid] = 0;

    const float4* xr = x4 + (size_t)row * IN_G;
    float m = 0.f;
    #pragma unroll 5
    for (int k = 0; k < QK; k++) {
        float4 v = xr[tid + k * QT];
        m = fmaxf(m, fmaxf(fmaxf(fabsf(v.x), fabsf(v.y)),
                           fmaxf(fabsf(v.z), fabsf(v.w))));
    }
    #pragma unroll
    for (int d = 16; d; d >>= 1) m = fmaxf(m, __shfl_down_sync(0xffffffffu, m, d));
    __shared__ float red[QT / 32];
    int warp = tid >> 5, lane = tid & 31;
    if (lane == 0) red[warp] = m;
    __syncthreads();
    if (tid < 32) {
        float v = (tid < QT / 32) ? red[tid] : 0.f;
        #pragma unroll
        for (int d = 16; d; d >>= 1) v = fmaxf(v, __shfl_down_sync(0xffffffffu, v, d));
        if (tid == 0) g_rowscale[row] = 127.f / fmaxf(v, 1e-5f);
    }
}

// magic-number quantize of a float4 into packed int8x4.
// FMUL+FADD(1.5*2^23) reproduces round-half-even of fl(x*s) exactly for |x*s|<=127.
// (validated: rel_err 5.9e-07 in round 3)
__device__ __forceinline__ unsigned quant_pack(float4 v, float as) {
    float f0 = __fadd_rn(__fmul_rn(v.x, as), 12582912.f);
    float f1 = __fadd_rn(__fmul_rn(v.y, as), 12582912.f);
    float f2 = __fadd_rn(__fmul_rn(v.z, as), 12582912.f);
    float f3 = __fadd_rn(__fmul_rn(v.w, as), 12582912.f);
    unsigned p01 = __byte_perm(__float_as_uint(f0), __float_as_uint(f1), 0x0040);
    unsigned p23 = __byte_perm(__float_as_uint(f2), __float_as_uint(f3), 0x0040);
    return __byte_perm(p01, p23, 0x5410);
}

// ---------------- kernel 5: fused quantize + ternary GEMV ----------------
// Reads fp32 x directly (second DRAM pass). No syncthreads in the row loop:
// REDUX.SUM warp reduce + lane0 integer atomicAdd (exact in int32).
__global__ void __launch_bounds__(GT, 2) k_gemv(const float4* __restrict__ x4) {
    extern __shared__ unsigned sw[];   // [10][GPT][GT]

    const int s = blockIdx.x;
    const int rb = blockIdx.y;
    const int tid = threadIdx.x;
    const int lane = tid & 31;
    const int gbase = s * SLICE_G;

    // one-time weight staging (L2-resident source)
    #pragma unroll
    for (int o = 0; o < OUT_FEAT; o++)
        #pragma unroll
        for (int k = 0; k < GPT; k++)
            sw[(o * GPT + k) * GT + tid] = g_tw[o * IN_G + gbase + k * GT + tid];
    __syncthreads();

    for (int row = rb; row < B_ROWS; row += ROWBLKS) {
        const float as = g_rowscale[row];
        const float4* xr = x4 + (size_t)row * IN_G + gbase;

        // load this thread's 5 float4 (coalesced 7.68KB runs)
        float4 v[GPT];
        #pragma unroll
        for (int k = 0; k < GPT; k++) v[k] = xr[k * GT + tid];

        int acc[OUT_FEAT];
        #pragma unroll
        for (int o = 0; o < OUT_FEAT; o++) acc[o] = 0;

        #pragma unroll
        for (int k = 0; k < GPT; k++) {
            unsigned qw = quant_pack(v[k], as);
            #pragma unroll
            for (int o = 0; o < OUT_FEAT; o++)
                acc[o] = __dp4a((int)qw, (int)sw[(o * GPT + k) * GT + tid], acc[o]);
        }

        #pragma unroll
        for (int o = 0; o < OUT_FEAT; o++)
            acc[o] = __reduce_add_sync(0xffffffffu, acc[o]);
        if (lane == 0) {
            int* dst = g_dot + row * OUT_FEAT;
            #pragma unroll
            for (int o = 0; o < OUT_FEAT; o++) atomicAdd(dst + o, acc[o]);
        }
    }
}

// ---------------- kernel 6: scale, bias, softmax ----------------
__global__ void k_finish(const float* __restrict__ bias, float* __restrict__ out) {
    int row = blockIdx.x * 128 + threadIdx.x;   // grid 8 x 128
    float inv_as = 1.f / g_rowscale[row];
    float coef = inv_as * g_winv;
    const int* dp = g_dot + row * OUT_FEAT;
    float logit[OUT_FEAT];
    float m = -3.4e38f;
    #pragma unroll
    for (int o = 0; o < OUT_FEAT; o++) {
        logit[o] = coef * (float)dp[o] + bias[o];
        m = fmaxf(m, logit[o]);
    }
    float ssum = 0.f;
    #pragma unroll
    for (int o = 0; o < OUT_FEAT; o++) { logit[o] = expf(logit[o] - m); ssum += logit[o]; }
    float inv_s = 1.f / ssum;
    #pragma unroll
    for (int o = 0; o < OUT_FEAT; o++) out[row * OUT_FEAT + o] = logit[o] * inv_s;
}

// ---------------- launch (fork/join: weight chain overlaps rowmax) ----------------
extern "C" void kernel_launch(void* const* d_in, const int* in_sizes, int n_in,
                              void* d_out, int out_size) {
    const float4* x4 = (const float4*)d_in[0];   // [1024,3,160,160] fp32
    const float4* w4 = (const float4*)d_in[1];   // [10,76800] fp32
    const float*  b  = (const float*)d_in[2];    // [10]
    float* out = (float*)d_out;

    static cudaStream_t s_side = nullptr;
    static cudaEvent_t ev_fork = nullptr, ev_join = nullptr;
    static int init_done = 0;
    if (!init_done) {   // first call is the non-captured correctness run
        cudaStreamCreateWithFlags(&s_side, cudaStreamNonBlocking);
        cudaEventCreateWithFlags(&ev_fork, cudaEventDisableTiming);
        cudaEventCreateWithFlags(&ev_join, cudaEventDisableTiming);
        cudaFuncSetAttribute(k_gemv, cudaFuncAttributeMaxDynamicSharedMemorySize, GEMV_SMEM);
        init_done = 1;
    }

    // fork: weight-prep chain on side stream, concurrent with k_rowmax
    cudaEventRecord(ev_fork, 0);
    cudaStreamWaitEvent(s_side, ev_fork, 0);
    k_wsum<<<WSUM_BLOCKS, WSUM_THREADS, 0, s_side>>>(w4);
    k_wscale<<<1, 128, 0, s_side>>>();
    k_ternary<<<W_G / 256, 256, 0, s_side>>>(w4);
    cudaEventRecord(ev_join, s_side);

    k_rowmax<<<B_ROWS, QT>>>(x4);                 // stream 0, ~47us, hides the chain

    cudaStreamWaitEvent(0, ev_join, 0);           // join before gemv needs g_tw
    dim3 ggrid(NSLICE, ROWBLKS);
    k_gemv<<<ggrid, GT, GEMV_SMEM>>>(x4);
    k_finish<<<B_ROWS / 128, 128>>>(b, out);
}